// round 13
// baseline (speedup 1.0000x reference)
#include <cuda_runtime.h>
#include <cuda_bf16.h>

// ---------------------------------------------------------------------------
// Seq2SeqDaVinciNet: persistent per-batch-tile kernel, f32x2-packed.
// B=4096, S=64, D=9, H=128, HZ=32.  grid = 256 blocks x 256 threads,
// each block owns MB=16 rows; TWO blocks per SM so barrier bubbles overlap.
// Row-PAIRS packed into 64-bit f32x2 regs.  EncH/AEt streams: bf16x2 pairs.
// Gate weight tables PRE-DUPLICATED ulonglong2 {w,w} pairs -> zero-MOV FFMA2.
// Shfl-parallel softmax / s6.
// ---------------------------------------------------------------------------

#define kB   4096
#define kS   64
#define kD   9
#define kH   128
#define kHZ  32
#define MB_  16
#define NT_  256
#define kDT  0.1f

typedef unsigned long long ull;

// ---- scratch (device globals) ---------------------------------------------
__device__ __nv_bfloat162 g_EncHbf[(kB/2) * kS * kH];  // [bpair][s][h]
__device__ __nv_bfloat162 g_AEtbf [(kB/2) * kH * kS];  // [bpair][h][s]
__device__ float  g_Att[kB * kD * kS];        // [b][d][tt]
__device__ __nv_bfloat16 g_WeTb[256 * 64];    // [k][s]
__device__ __nv_bfloat16 g_WdTb[256 * 128];   // [k][ho]
__device__ ulonglong2 g_Wenc8 [kH * kH * 2];  // [k][j][2]: {wi,wi,wf,wf},{wg,wg,wo,wo}
__device__ ulonglong2 g_Wencx8[kD * kH * 2];  // [d][j][2]
__device__ ulonglong2 g_Wdec8 [265 * kH * 2]; // [kk][j][2]
__device__ ull        g_Vd2   [kH * kH];      // [k][ho] dup pair

// ---- shared memory layout (float offsets) ---------------------------------
#define OFF_HP    0                 // [128][9] float2  pairs
#define OFF_CP    2304              // [128][9] float2
#define OFF_AP    4608              // [128][9] float2
#define OFF_LOG   6912              // [64][18] float
#define OFF_EDP   8256              // [9][18]
#define OFF_PHY   8418              // [9][18]
#define OFF_POS   8580              // [16][4]
#define OFF_VEL   8644
#define OFF_ACC   8708
#define OFF_VE    8772              // 64
#define OFF_VD    8836              // 128
#define OFF_SC    8964              // 16
#define OFF_BIAS  8980              // 512
#define OFF_WO    9492              // 768
#define OFF_BO    10260             // 8
#define OFF_UNION 10272
#define U_ATT  0
#define U_WET  9360
#define U_WDT  0
#define UNION_SZ 17680
#define SMEM_FLOATS (OFF_UNION + UNION_SZ)
#define SMEM_BYTES  (SMEM_FLOATS * 4)     // 111808 B -> 2 CTAs/SM

// ---- math helpers ---------------------------------------------------------
__device__ __forceinline__ float tanhfast(float x) {
    float y; asm("tanh.approx.f32 %0, %1;" : "=f"(y) : "f"(x)); return y;
}
__device__ __forceinline__ float sigm(float x) {        // 0.5*tanh(x/2)+0.5
    return fmaf(0.5f, tanhfast(0.5f * x), 0.5f);
}
__device__ __forceinline__ ull pk2(float lo, float hi) {
    ull r;
    asm("mov.b64 %0,{%1,%2};" : "=l"(r) : "r"(__float_as_int(lo)), "r"(__float_as_int(hi)));
    return r;
}
__device__ __forceinline__ void upk2(ull v, float& lo, float& hi) {
    int a, b;
    asm("mov.b64 {%0,%1},%2;" : "=r"(a), "=r"(b) : "l"(v));
    lo = __int_as_float(a); hi = __int_as_float(b);
}
__device__ __forceinline__ ull ffma2(ull a, ull b, ull c) {
    ull d; asm("fma.rn.f32x2 %0,%1,%2,%3;" : "=l"(d) : "l"(a), "l"(b), "l"(c)); return d;
}
__device__ __forceinline__ ull ldp(const float* p) {           // LDS.64 pair
    return *reinterpret_cast<const ull*>(p);
}
__device__ __forceinline__ void stp(float* p, ull v) {
    *reinterpret_cast<ull*>(p) = v;
}

// ---- prep: repack weights -------------------------------------------------
__device__ __forceinline__ ull dupw(float w) {
    unsigned u = __float_as_uint(w);
    return (ull)u | ((ull)u << 32);
}

__global__ void prep_kernel(const float* __restrict__ Whh_e,
                            const float* __restrict__ Wih_e,
                            const float* __restrict__ Whh_d,
                            const float* __restrict__ Wih_d,
                            const float* __restrict__ Vd,
                            const float* __restrict__ We,
                            const float* __restrict__ Wd) {
    int i = blockIdx.x * blockDim.x + threadIdx.x;
    if (i < 128 * 128) {                    // g_Wenc8[k][j]
        int k = i >> 7, j = i & 127;
        g_Wenc8[i * 2]     = make_ulonglong2(dupw(Whh_e[j * 128 + k]),
                                             dupw(Whh_e[(128 + j) * 128 + k]));
        g_Wenc8[i * 2 + 1] = make_ulonglong2(dupw(Whh_e[(256 + j) * 128 + k]),
                                             dupw(Whh_e[(384 + j) * 128 + k]));
        g_Vd2[i] = dupw(Vd[(i & 127) * 128 + (i >> 7)]);   // [k][ho] <- Vd[ho][k]
    }
    if (i < 9 * 128) {                      // g_Wencx8[d][j]
        int d = i >> 7, j = i & 127;
        g_Wencx8[i * 2]     = make_ulonglong2(dupw(Wih_e[j * 9 + d]),
                                              dupw(Wih_e[(128 + j) * 9 + d]));
        g_Wencx8[i * 2 + 1] = make_ulonglong2(dupw(Wih_e[(256 + j) * 9 + d]),
                                              dupw(Wih_e[(384 + j) * 9 + d]));
    }
    if (i < 265 * 128) {                    // g_Wdec8[kk][j]
        int kk = i >> 7, j = i & 127;
        if (kk < 137) {
            g_Wdec8[i * 2]     = make_ulonglong2(dupw(Wih_d[j * 137 + kk]),
                                                 dupw(Wih_d[(128 + j) * 137 + kk]));
            g_Wdec8[i * 2 + 1] = make_ulonglong2(dupw(Wih_d[(256 + j) * 137 + kk]),
                                                 dupw(Wih_d[(384 + j) * 137 + kk]));
        } else {
            int k = kk - 137;
            g_Wdec8[i * 2]     = make_ulonglong2(dupw(Whh_d[j * 128 + k]),
                                                 dupw(Whh_d[(128 + j) * 128 + k]));
            g_Wdec8[i * 2 + 1] = make_ulonglong2(dupw(Whh_d[(256 + j) * 128 + k]),
                                                 dupw(Whh_d[(384 + j) * 128 + k]));
        }
    }
    if (i < 256 * 64) {                     // g_WeTb[k][s] = bf16(We[s][k])
        int k = i >> 6, s = i & 63;
        g_WeTb[i] = __float2bfloat16(We[s * 256 + k]);
    }
    if (i < 256 * 128) {                    // g_WdTb[k][ho] = bf16(Wd[ho][k])
        int k = i >> 7, ho = i & 127;
        g_WdTb[i] = __float2bfloat16(Wd[ho * 256 + k]);
    }
}

// ---- prep: attn_input[b][d][tt] = sum_s Ve[tt][s] * x[b][s][d] ------------
__global__ void att_kernel(const float* __restrict__ x,
                           const float* __restrict__ Ve) {
    __shared__ float xr[kS * kD];
    const int b = blockIdx.x;
    const int t = threadIdx.x;            // 576 threads
    xr[t] = x[(size_t)b * (kS * kD) + t];
    __syncthreads();
    const int d = t / kS, tt = t % kS;
    float acc = 0.f;
    #pragma unroll 8
    for (int s = 0; s < kS; s++)
        acc += Ve[tt * kS + s] * xr[s * kD + d];
    g_Att[((size_t)b * kD + d) * kS + tt] = acc;
}

// ---- main fused kernel ----------------------------------------------------
__global__ __launch_bounds__(NT_, 2)
void davinci_kernel(const float* __restrict__ x,
                    const float* __restrict__ bih_e, const float* __restrict__ bhh_e,
                    const float* __restrict__ ve,
                    const float* __restrict__ vd,
                    const float* __restrict__ bih_d, const float* __restrict__ bhh_d,
                    const float* __restrict__ Wout, const float* __restrict__ bout,
                    const float* __restrict__ smean, const float* __restrict__ sstd,
                    const float* __restrict__ pmean,
                    float* __restrict__ out) {
    extern __shared__ float sm[];
    const int t   = threadIdx.x;
    const int b0  = blockIdx.x * MB_;
    const int bp0 = blockIdx.x * (MB_ / 2);       // pair base (8 pairs/block)

    float* sHpf = sm + OFF_HP;     // [128][9] f2 -> float idx (k*9+p)*2
    float* sCpf = sm + OFF_CP;
    float* sApf = sm + OFF_AP;
    float* sLgf = sm + OFF_LOG;    // [64][18]
    float* sEDp = sm + OFF_EDP;    // [9][18]
    float* sPhy = sm + OFF_PHY;    // [9][18]
    float* sPos = sm + OFF_POS;
    float* sVel = sm + OFF_VEL;
    float* sAcc = sm + OFF_ACC;
    float* sVe  = sm + OFF_VE;
    float* sVd  = sm + OFF_VD;
    float* sSc  = sm + OFF_SC;
    float* sBias= sm + OFF_BIAS;
    float* sWo  = sm + OFF_WO;
    float* sBo  = sm + OFF_BO;
    float* uni  = sm + OFF_UNION;
    float* sAtt = uni + U_ATT;                              // [16][9][65] f32
    __nv_bfloat16* sWeTb = (__nv_bfloat16*)(uni + U_WET);   // [256][65] bf16
    __nv_bfloat16* sWdTb = (__nv_bfloat16*)(uni + U_WDT);   // [256][129] bf16

    // ======================= prologue ======================================
    if (t < 64)  sVe[t] = ve[t];
    if (t < 128) sVd[t] = vd[t];
    if (t < 9)   sSc[t] = (t < 3) ? smean[t] : (t < 6 ? sstd[t - 3] : pmean[t - 6]);
    if (t < 256) { sBias[t] = bih_e[t] + bhh_e[t]; sBias[256 + t] = bih_e[256 + t] + bhh_e[256 + t]; }

    for (int i = t; i < MB_ * kD * kS; i += NT_)           // 9216, contiguous
        sAtt[(i >> 6) * 65 + (i & 63)] = g_Att[(size_t)b0 * (kD * kS) + i];
    for (int i = t; i < 256 * 64; i += NT_) {
        int k = i >> 6, s = i & 63;
        sWeTb[k * 65 + s] = g_WeTb[i];
    }
    if (t < MB_) {
        const float* xr = x + (size_t)(b0 + t) * (kS * kD);
        #pragma unroll
        for (int m = 0; m < 3; m++) {
            float p  = xr[63 * 9 + m] + sSc[6 + m];
            float v  = xr[63 * 9 + 3 + m] * sSc[3 + m] + sSc[m];
            float pv = xr[62 * 9 + 3 + m] * sSc[3 + m] + sSc[m];
            sPos[t * 4 + m] = p;
            sVel[t * 4 + m] = v;
            sAcc[t * 4 + m] = (v - pv) * (1.0f / kDT);
        }
    }
    for (int i = t; i < 2304; i += NT_) { sHpf[i] = 0.f; sCpf[i] = 0.f; }
    __syncthreads();

    // ======================= encoder loop ==================================
    for (int ts = 0; ts < kS; ts++) {
        // --- stage1: a[r][s] = W_e[s] . [h;c]  (4 rows = 2 pairs / thread)
        {
            const int s  = t & 63;
            const int pg = (t >> 6) * 2;       // 0,2,4,6
            ull a0 = 0ull, a1 = 0ull;
            #pragma unroll 4
            for (int k = 0; k < 128; k++) {
                float w = __bfloat162float(sWeTb[k * 65 + s]);
                ull w2 = pk2(w, w);
                a0 = ffma2(w2, ldp(sHpf + (k * 9 + pg) * 2), a0);
                a1 = ffma2(w2, ldp(sHpf + (k * 9 + pg + 1) * 2), a1);
            }
            #pragma unroll 4
            for (int k = 0; k < 128; k++) {
                float w = __bfloat162float(sWeTb[(128 + k) * 65 + s]);
                ull w2 = pk2(w, w);
                a0 = ffma2(w2, ldp(sCpf + (k * 9 + pg) * 2), a0);
                a1 = ffma2(w2, ldp(sCpf + (k * 9 + pg + 1) * 2), a1);
            }
            stp(sApf + (s * 9 + pg) * 2, a0);
            stp(sApf + (s * 9 + pg + 1) * 2, a1);
        }
        __syncthreads();
        // --- stage2+3 fused: e, softmax over d (shfl, 16-lane groups),
        //     x_tilde -> sEDp[d][r]
        {
            const int r = t >> 4;        // 0..15
            const int l = t & 15;        // lane in group; d = l for l<9
            float e = -1e30f;
            if (l < 9) {
                float acc = 0.f;
                #pragma unroll 4
                for (int s2 = 0; s2 < 64; s2++) {
                    float z = sApf[s2 * 18 + r] + sAtt[(r * 9 + l) * 65 + s2];
                    acc += sVe[s2] * tanhfast(z);
                }
                e = acc;
            }
            float mx = e;
            #pragma unroll
            for (int o = 8; o; o >>= 1)
                mx = fmaxf(mx, __shfl_xor_sync(0xffffffffu, mx, o, 16));
            float ex = (l < 9) ? __expf(e - mx) : 0.f;
            float sum = ex;
            #pragma unroll
            for (int o = 8; o; o >>= 1)
                sum += __shfl_xor_sync(0xffffffffu, sum, o, 16);
            if (l < 9) {
                float xv = x[(size_t)(b0 + r) * (kS * kD) + ts * kD + l];
                sEDp[l * 18 + r] = __fdividef(ex, sum) * xv;
            }
        }
        __syncthreads();
        // --- stage4: gates + LSTM update; stage5: V_d . h
        {
            const int j  = t & 127;
            const int p0 = (t >> 7) * 4;          // 0 or 4 : 4 pairs = 8 rows
            ull acc[16];                          // [gate][pair]
            {
                ull bi = pk2(sBias[j], sBias[j]);
                ull bf = pk2(sBias[128 + j], sBias[128 + j]);
                ull bg = pk2(sBias[256 + j], sBias[256 + j]);
                ull bo = pk2(sBias[384 + j], sBias[384 + j]);
                #pragma unroll
                for (int p = 0; p < 4; p++) {
                    acc[p] = bi; acc[4 + p] = bf; acc[8 + p] = bg; acc[12 + p] = bo;
                }
            }
            #pragma unroll
            for (int d = 0; d < 9; d++) {
                ulonglong2 wa = g_Wencx8[(d * 128 + j) * 2];
                ulonglong2 wb = g_Wencx8[(d * 128 + j) * 2 + 1];
                #pragma unroll
                for (int p = 0; p < 4; p++) {
                    ull xv = ldp(sEDp + d * 18 + 2 * (p0 + p));
                    acc[p]      = ffma2(wa.x, xv, acc[p]);
                    acc[4 + p]  = ffma2(wa.y, xv, acc[4 + p]);
                    acc[8 + p]  = ffma2(wb.x, xv, acc[8 + p]);
                    acc[12 + p] = ffma2(wb.y, xv, acc[12 + p]);
                }
            }
            #pragma unroll 4
            for (int k = 0; k < 128; k++) {
                ulonglong2 wa = g_Wenc8[(k * 128 + j) * 2];
                ulonglong2 wb = g_Wenc8[(k * 128 + j) * 2 + 1];
                #pragma unroll
                for (int p = 0; p < 4; p++) {
                    ull hv = ldp(sHpf + (k * 9 + p0 + p) * 2);
                    acc[p]      = ffma2(wa.x, hv, acc[p]);
                    acc[4 + p]  = ffma2(wa.y, hv, acc[4 + p]);
                    acc[8 + p]  = ffma2(wb.x, hv, acc[8 + p]);
                    acc[12 + p] = ffma2(wb.y, hv, acc[12 + p]);
                }
            }
            __syncthreads();
            #pragma unroll
            for (int p = 0; p < 4; p++) {
                float ai0, ai1, af0, af1, ag0, ag1, ao0, ao1, c0, c1;
                upk2(acc[p], ai0, ai1);  upk2(acc[4 + p], af0, af1);
                upk2(acc[8 + p], ag0, ag1); upk2(acc[12 + p], ao0, ao1);
                upk2(ldp(sCpf + (j * 9 + p0 + p) * 2), c0, c1);
                float cn0 = sigm(af0) * c0 + sigm(ai0) * tanhfast(ag0);
                float cn1 = sigm(af1) * c1 + sigm(ai1) * tanhfast(ag1);
                float hn0 = sigm(ao0) * tanhfast(cn0);
                float hn1 = sigm(ao1) * tanhfast(cn1);
                stp(sCpf + (j * 9 + p0 + p) * 2, pk2(cn0, cn1));
                stp(sHpf + (j * 9 + p0 + p) * 2, pk2(hn0, hn1));
                g_EncHbf[((size_t)(bp0 + p0 + p) * kS + ts) * kH + j] =
                    __float22bfloat162_rn(make_float2(hn0, hn1));
            }
            __syncthreads();
            // stage5: A[r][ho] = V_d[ho] . h  -> g_AEtbf transposed, pair bf16
            ull a5[4] = {0ull, 0ull, 0ull, 0ull};
            #pragma unroll 4
            for (int k = 0; k < 128; k++) {
                ull w2 = g_Vd2[k * 128 + j];
                #pragma unroll
                for (int p = 0; p < 4; p++)
                    a5[p] = ffma2(w2, ldp(sHpf + (k * 9 + p0 + p) * 2), a5[p]);
            }
            #pragma unroll
            for (int p = 0; p < 4; p++) {
                float lo, hi; upk2(a5[p], lo, hi);
                g_AEtbf[((size_t)(bp0 + p0 + p) * kH + j) * kS + ts] =
                    __float22bfloat162_rn(make_float2(lo, hi));
            }
        }
        // NOTE: no end-of-step barrier needed — stage5 and next stage1 only
        // READ sHpf/sCpf; stage1's write target (sApf) is untouched by stage5,
        // and the next write to sHpf is 3 barriers away.
    }
    __syncthreads();

    // ======================= decoder weight reload =========================
    for (int i = t; i < 256 * 128; i += NT_) {          // Wd^T bf16 into union
        int k = i >> 7, ho = i & 127;
        sWdTb[k * 129 + ho] = g_WdTb[i];
    }
    if (t < 256) { sBias[t] = bih_d[t] + bhh_d[t]; sBias[256 + t] = bih_d[256 + t] + bhh_d[256 + t]; }
    for (int i = t; i < 768; i += NT_) sWo[i] = Wout[i];
    if (t < 3) sBo[t] = bout[t];
    __syncthreads();

    // ======================= decoder loop ==================================
    for (int st = 0; st < kHZ; st++) {
        // --- s1: a[r][ho] = W_d[ho] . [d;c]   (8 rows = 4 pairs)
        {
            const int ho = t & 127;
            const int p0 = (t >> 7) * 4;
            ull a[4] = {0ull, 0ull, 0ull, 0ull};
            #pragma unroll 4
            for (int k = 0; k < 128; k++) {
                float w = __bfloat162float(sWdTb[k * 129 + ho]);
                ull w2 = pk2(w, w);
                #pragma unroll
                for (int p = 0; p < 4; p++)
                    a[p] = ffma2(w2, ldp(sHpf + (k * 9 + p0 + p) * 2), a[p]);
            }
            #pragma unroll 4
            for (int k = 0; k < 128; k++) {
                float w = __bfloat162float(sWdTb[(128 + k) * 129 + ho]);
                ull w2 = pk2(w, w);
                #pragma unroll
                for (int p = 0; p < 4; p++)
                    a[p] = ffma2(w2, ldp(sCpf + (k * 9 + p0 + p) * 2), a[p]);
            }
            #pragma unroll
            for (int p = 0; p < 4; p++) stp(sApf + (ho * 9 + p0 + p) * 2, a[p]);
        }
        __syncthreads();
        // --- s2: logits[r][s] = sum_ho v_d[ho]*tanh(a[r][ho] + AEt[ho][s])
        {
            const int s  = t & 63;
            const int g  = t >> 6;                 // 0..3
            const int r0 = g * 4;                  // rows r0..r0+3 = pairs 2g,2g+1
            float l0 = 0.f, l1 = 0.f, l2 = 0.f, l3 = 0.f;
            const __nv_bfloat162* aet0 =
                g_AEtbf + ((size_t)(bp0 + 2 * g) * kH) * kS + s;
            const __nv_bfloat162* aet1 = aet0 + (size_t)kH * kS;
            #pragma unroll 8
            for (int ho = 0; ho < 128; ho++) {
                float2 v0 = __bfloat1622float2(aet0[ho * kS]);
                float2 v1 = __bfloat1622float2(aet1[ho * kS]);
                float w  = sVd[ho];
                float a0 = sApf[ho * 18 + r0];
                float a1 = sApf[ho * 18 + r0 + 1];
                float a2 = sApf[ho * 18 + r0 + 2];
                float a3 = sApf[ho * 18 + r0 + 3];
                l0 += w * tanhfast(a0 + v0.x);
                l1 += w * tanhfast(a1 + v0.y);
                l2 += w * tanhfast(a2 + v1.x);
                l3 += w * tanhfast(a3 + v1.y);
            }
            sLgf[s * 18 + r0]     = l0;
            sLgf[s * 18 + r0 + 1] = l1;
            sLgf[s * 18 + r0 + 2] = l2;
            sLgf[s * 18 + r0 + 3] = l3;
        }
        __syncthreads();
        // --- s3: softmax beta over s (shfl, 16-lane groups, 4 s per lane);
        //     phys vector
        {
            const int r = t >> 4;
            const int l = t & 15;
            float v0 = sLgf[l * 18 + r];
            float v1 = sLgf[(l + 16) * 18 + r];
            float v2 = sLgf[(l + 32) * 18 + r];
            float v3 = sLgf[(l + 48) * 18 + r];
            float mx = fmaxf(fmaxf(v0, v1), fmaxf(v2, v3));
            #pragma unroll
            for (int o = 8; o; o >>= 1)
                mx = fmaxf(mx, __shfl_xor_sync(0xffffffffu, mx, o, 16));
            v0 = __expf(v0 - mx); v1 = __expf(v1 - mx);
            v2 = __expf(v2 - mx); v3 = __expf(v3 - mx);
            float sum = (v0 + v1) + (v2 + v3);
            #pragma unroll
            for (int o = 8; o; o >>= 1)
                sum += __shfl_xor_sync(0xffffffffu, sum, o, 16);
            float inv = __fdividef(1.f, sum);
            sLgf[l * 18 + r]        = v0 * inv;
            sLgf[(l + 16) * 18 + r] = v1 * inv;
            sLgf[(l + 32) * 18 + r] = v2 * inv;
            sLgf[(l + 48) * 18 + r] = v3 * inv;
            if (l < 9) {
                const int grp = l / 3, m = l % 3;
                float val;
                if (grp == 0)      val = sPos[r * 4 + m] - sSc[6 + m];
                else if (grp == 1) val = __fdividef(sVel[r * 4 + m] - sSc[m], sSc[3 + m]);
                else               val = __fdividef(sAcc[r * 4 + m], sSc[3 + m]);
                sPhy[l * 18 + r] = val;
            }
        }
        __syncthreads();
        // --- s4: context[r][ho] = sum_s beta[r][s]*EncH  (bf16 pairs)
        {
            const int ho = t & 127;
            const int p0 = (t >> 7) * 4;
            ull a[4] = {0ull, 0ull, 0ull, 0ull};
            const __nv_bfloat162* eh =
                g_EncHbf + ((size_t)(bp0 + p0) * kS) * kH + ho;
            #pragma unroll 8
            for (int s2 = 0; s2 < 64; s2++) {
                #pragma unroll
                for (int p = 0; p < 4; p++) {
                    float2 h2 = __bfloat1622float2(eh[(p * kS + s2) * kH]);
                    ull bv = ldp(sLgf + s2 * 18 + 2 * (p0 + p));
                    a[p] = ffma2(bv, pk2(h2.x, h2.y), a[p]);
                }
            }
            #pragma unroll
            for (int p = 0; p < 4; p++) stp(sApf + (ho * 9 + p0 + p) * 2, a[p]);
        }
        __syncthreads();
        // --- s5: decoder gates + LSTM update
        {
            const int j  = t & 127;
            const int p0 = (t >> 7) * 4;
            ull acc[16];
            {
                ull bi = pk2(sBias[j], sBias[j]);
                ull bf = pk2(sBias[128 + j], sBias[128 + j]);
                ull bg = pk2(sBias[256 + j], sBias[256 + j]);
                ull bo = pk2(sBias[384 + j], sBias[384 + j]);
                #pragma unroll
                for (int p = 0; p < 4; p++) {
                    acc[p] = bi; acc[4 + p] = bf; acc[8 + p] = bg; acc[12 + p] = bo;
                }
            }
            #pragma unroll
            for (int d = 0; d < 9; d++) {
                ulonglong2 wa = g_Wdec8[(d * 128 + j) * 2];
                ulonglong2 wb = g_Wdec8[(d * 128 + j) * 2 + 1];
                #pragma unroll
                for (int p = 0; p < 4; p++) {
                    ull xv = ldp(sPhy + d * 18 + 2 * (p0 + p));
                    acc[p]      = ffma2(wa.x, xv, acc[p]);
                    acc[4 + p]  = ffma2(wa.y, xv, acc[4 + p]);
                    acc[8 + p]  = ffma2(wb.x, xv, acc[8 + p]);
                    acc[12 + p] = ffma2(wb.y, xv, acc[12 + p]);
                }
            }
            #pragma unroll 4
            for (int k = 0; k < 128; k++) {         // context part
                ulonglong2 wa = g_Wdec8[((9 + k) * 128 + j) * 2];
                ulonglong2 wb = g_Wdec8[((9 + k) * 128 + j) * 2 + 1];
                #pragma unroll
                for (int p = 0; p < 4; p++) {
                    ull xv = ldp(sApf + (k * 9 + p0 + p) * 2);
                    acc[p]      = ffma2(wa.x, xv, acc[p]);
                    acc[4 + p]  = ffma2(wa.y, xv, acc[4 + p]);
                    acc[8 + p]  = ffma2(wb.x, xv, acc[8 + p]);
                    acc[12 + p] = ffma2(wb.y, xv, acc[12 + p]);
                }
            }
            #pragma unroll 4
            for (int k = 0; k < 128; k++) {         // h part
                ulonglong2 wa = g_Wdec8[((137 + k) * 128 + j) * 2];
                ulonglong2 wb = g_Wdec8[((137 + k) * 128 + j) * 2 + 1];
                #pragma unroll
                for (int p = 0; p < 4; p++) {
                    ull hv = ldp(sHpf + (k * 9 + p0 + p) * 2);
                    acc[p]      = ffma2(wa.x, hv, acc[p]);
                    acc[4 + p]  = ffma2(wa.y, hv, acc[4 + p]);
                    acc[8 + p]  = ffma2(wb.x, hv, acc[8 + p]);
                    acc[12 + p] = ffma2(wb.y, hv, acc[12 + p]);
                }
            }
            __syncthreads();
            #pragma unroll
            for (int p = 0; p < 4; p++) {
                float ai0, ai1, af0, af1, ag0, ag1, ao0, ao1, c0, c1;
                upk2(acc[p], ai0, ai1);  upk2(acc[4 + p], af0, af1);
                upk2(acc[8 + p], ag0, ag1); upk2(acc[12 + p], ao0, ao1);
                upk2(ldp(sCpf + (j * 9 + p0 + p) * 2), c0, c1);
                float cn0 = sigm(af0) * c0 + sigm(ai0) * tanhfast(ag0);
                float cn1 = sigm(af1) * c1 + sigm(ai1) * tanhfast(ag1);
                float dn0 = sigm(ao0) * tanhfast(cn0);
                float dn1 = sigm(ao1) * tanhfast(cn1);
                stp(sCpf + (j * 9 + p0 + p) * 2, pk2(cn0, cn1));
                stp(sHpf + (j * 9 + p0 + p) * 2, pk2(dn0, dn1));
            }
        }
        __syncthreads();
        // --- s6: pred_acc + Verlet + output (192 threads, quad-split dots)
        if (t < 192) {
            const int q = t & 3;           // quad lane
            const int o = t >> 2;          // 0..47
            const int m = o >> 4;          // 0..2
            const int r = o & 15;
            const float* src = (q < 2) ? sHpf : sApf;
            const int kbase = (q & 1) * 64;
            const float* w = sWo + m * 256 + (q >> 1) * 128 + kbase;
            float acc = 0.f;
            #pragma unroll 4
            for (int kk = 0; kk < 64; kk++)
                acc += w[kk] * src[(kbase + kk) * 18 + r];
            acc += __shfl_xor_sync(0xffffffffu, acc, 1, 4);
            acc += __shfl_xor_sync(0xffffffffu, acc, 2, 4);
            if (q == 0) {
                acc += sBo[m];
                float pa   = acc * sSc[3 + m];
                float pos  = sPos[r * 4 + m];
                float vel  = sVel[r * 4 + m];
                float ac   = sAcc[r * 4 + m];
                float posn = pos + vel * kDT + 0.5f * ac * kDT * kDT;
                float veln = vel + 0.5f * (ac + pa) * kDT;
                float* orow = out + ((size_t)(b0 + r) * kHZ + st) * 9;
                orow[m]     = posn;
                orow[3 + m] = veln;
                orow[6 + m] = pa;
                sPos[r * 4 + m] = posn;
                sVel[r * 4 + m] = veln;
                sAcc[r * 4 + m] = pa;
            }
        }
        __syncthreads();
    }
}

// ---------------------------------------------------------------------------
extern "C" void kernel_launch(void* const* d_in, const int* in_sizes, int n_in,
                              void* d_out, int out_size) {
    const float* x      = (const float*)d_in[0];
    const float* Wih_e  = (const float*)d_in[1];
    const float* Whh_e  = (const float*)d_in[2];
    const float* bih_e  = (const float*)d_in[3];
    const float* bhh_e  = (const float*)d_in[4];
    const float* We     = (const float*)d_in[5];
    const float* Ve     = (const float*)d_in[6];
    const float* ve     = (const float*)d_in[7];
    const float* Wd     = (const float*)d_in[8];
    const float* Vd     = (const float*)d_in[9];
    const float* vd     = (const float*)d_in[10];
    const float* Wih_d  = (const float*)d_in[11];
    const float* Whh_d  = (const float*)d_in[12];
    const float* bih_d  = (const float*)d_in[13];
    const float* bhh_d  = (const float*)d_in[14];
    const float* Wout   = (const float*)d_in[15];
    const float* bout   = (const float*)d_in[16];
    const float* smean  = (const float*)d_in[17];
    const float* sstd   = (const float*)d_in[18];
    const float* pmean  = (const float*)d_in[19];
    float* out = (float*)d_out;

    cudaFuncSetAttribute(davinci_kernel,
                         cudaFuncAttributeMaxDynamicSharedMemorySize, SMEM_BYTES);

    prep_kernel<<<(265 * 128 + 255) / 256, 256>>>(Whh_e, Wih_e, Whh_d, Wih_d, Vd, We, Wd);
    att_kernel<<<kB, kS * kD>>>(x, Ve);
    davinci_kernel<<<kB / MB_, NT_, SMEM_BYTES>>>(
        x, bih_e, bhh_e, ve, vd,
        bih_d, bhh_d, Wout, bout, smean, sstd, pmean, out);
}

// round 14
// speedup vs baseline: 2.0201x; 2.0201x over previous
#include <cuda_runtime.h>
#include <cuda_bf16.h>

// ---------------------------------------------------------------------------
// Seq2SeqDaVinciNet: persistent per-batch-tile kernel, f32x2-packed.
// B=4096, S=64, D=9, H=128, HZ=32.  grid = 256 blocks x 256 threads,
// each block owns MB=16 rows; TWO blocks per SM so barrier bubbles overlap.
// Row-PAIRS packed into 64-bit f32x2 regs.  EncH/AEt streams: bf16x2 pairs.
// Gate weight tables fp32 float4 (16B/k/thread, one LDG.128 — proven optimum).
// Shfl-parallel softmax / s6.  Encoder end-of-step barrier elided.
// ---------------------------------------------------------------------------

#define kB   4096
#define kS   64
#define kD   9
#define kH   128
#define kHZ  32
#define MB_  16
#define NT_  256
#define kDT  0.1f

typedef unsigned long long ull;

// ---- scratch (device globals) ---------------------------------------------
__device__ __nv_bfloat162 g_EncHbf[(kB/2) * kS * kH];  // [bpair][s][h]
__device__ __nv_bfloat162 g_AEtbf [(kB/2) * kH * kS];  // [bpair][h][s]
__device__ float  g_Att[kB * kD * kS];        // [b][d][tt]
__device__ __nv_bfloat16 g_WeTb[256 * 64];    // [k][s]
__device__ __nv_bfloat16 g_WdTb[256 * 128];   // [k][ho]
__device__ float4 g_Wenc4 [kH * kH];          // [k][j]
__device__ float4 g_Wencx4[kD * kH];          // [d][j]
__device__ float4 g_Wdec4 [265 * kH];         // [kk][j]
__device__ float4 g_Vd4   [32 * kH];          // [k4][ho]

// ---- shared memory layout (float offsets) ---------------------------------
#define OFF_HP    0                 // [128][9] float2  pairs
#define OFF_CP    2304              // [128][9] float2
#define OFF_AP    4608              // [128][9] float2
#define OFF_LOG   6912              // [64][18] float
#define OFF_EDP   8256              // [9][18]
#define OFF_PHY   8418              // [9][18]
#define OFF_POS   8580              // [16][4]
#define OFF_VEL   8644
#define OFF_ACC   8708
#define OFF_VE    8772              // 64
#define OFF_VD    8836              // 128
#define OFF_SC    8964              // 16
#define OFF_BIAS  8980              // 512
#define OFF_WO    9492              // 768
#define OFF_BO    10260             // 8
#define OFF_UNION 10272
#define U_ATT  0
#define U_WET  9360
#define U_WDT  0
#define UNION_SZ 17680
#define SMEM_FLOATS (OFF_UNION + UNION_SZ)
#define SMEM_BYTES  (SMEM_FLOATS * 4)     // 111808 B -> 2 CTAs/SM

// ---- math helpers ---------------------------------------------------------
__device__ __forceinline__ float tanhfast(float x) {
    float y; asm("tanh.approx.f32 %0, %1;" : "=f"(y) : "f"(x)); return y;
}
__device__ __forceinline__ float sigm(float x) {        // 0.5*tanh(x/2)+0.5
    return fmaf(0.5f, tanhfast(0.5f * x), 0.5f);
}
__device__ __forceinline__ ull pk2(float lo, float hi) {
    ull r;
    asm("mov.b64 %0,{%1,%2};" : "=l"(r) : "r"(__float_as_int(lo)), "r"(__float_as_int(hi)));
    return r;
}
__device__ __forceinline__ void upk2(ull v, float& lo, float& hi) {
    int a, b;
    asm("mov.b64 {%0,%1},%2;" : "=r"(a), "=r"(b) : "l"(v));
    lo = __int_as_float(a); hi = __int_as_float(b);
}
__device__ __forceinline__ ull ffma2(ull a, ull b, ull c) {
    ull d; asm("fma.rn.f32x2 %0,%1,%2,%3;" : "=l"(d) : "l"(a), "l"(b), "l"(c)); return d;
}
__device__ __forceinline__ ull ldp(const float* p) {           // LDS.64 pair
    return *reinterpret_cast<const ull*>(p);
}
__device__ __forceinline__ void stp(float* p, ull v) {
    *reinterpret_cast<ull*>(p) = v;
}

// ---- prep: repack weights -------------------------------------------------
__global__ void prep_kernel(const float* __restrict__ Whh_e,
                            const float* __restrict__ Wih_e,
                            const float* __restrict__ Whh_d,
                            const float* __restrict__ Wih_d,
                            const float* __restrict__ Vd,
                            const float* __restrict__ We,
                            const float* __restrict__ Wd) {
    int i = blockIdx.x * blockDim.x + threadIdx.x;
    if (i < 128 * 128) {                    // g_Wenc4[k][j]
        int k = i >> 7, j = i & 127;
        g_Wenc4[i] = make_float4(Whh_e[j * 128 + k], Whh_e[(128 + j) * 128 + k],
                                 Whh_e[(256 + j) * 128 + k], Whh_e[(384 + j) * 128 + k]);
    }
    if (i < 9 * 128) {                      // g_Wencx4[d][j]
        int d = i >> 7, j = i & 127;
        g_Wencx4[i] = make_float4(Wih_e[j * 9 + d], Wih_e[(128 + j) * 9 + d],
                                  Wih_e[(256 + j) * 9 + d], Wih_e[(384 + j) * 9 + d]);
    }
    if (i < 265 * 128) {                    // g_Wdec4[kk][j]
        int kk = i >> 7, j = i & 127;
        if (kk < 137) {
            g_Wdec4[i] = make_float4(Wih_d[j * 137 + kk], Wih_d[(128 + j) * 137 + kk],
                                     Wih_d[(256 + j) * 137 + kk], Wih_d[(384 + j) * 137 + kk]);
        } else {
            int k = kk - 137;
            g_Wdec4[i] = make_float4(Whh_d[j * 128 + k], Whh_d[(128 + j) * 128 + k],
                                     Whh_d[(256 + j) * 128 + k], Whh_d[(384 + j) * 128 + k]);
        }
    }
    if (i < 32 * 128) {                     // g_Vd4[k4][ho]
        int k4 = i >> 7, ho = i & 127;
        g_Vd4[i] = make_float4(Vd[ho * 128 + 4 * k4],     Vd[ho * 128 + 4 * k4 + 1],
                               Vd[ho * 128 + 4 * k4 + 2], Vd[ho * 128 + 4 * k4 + 3]);
    }
    if (i < 256 * 64) {                     // g_WeTb[k][s] = bf16(We[s][k])
        int k = i >> 6, s = i & 63;
        g_WeTb[i] = __float2bfloat16(We[s * 256 + k]);
    }
    if (i < 256 * 128) {                    // g_WdTb[k][ho] = bf16(Wd[ho][k])
        int k = i >> 7, ho = i & 127;
        g_WdTb[i] = __float2bfloat16(Wd[ho * 256 + k]);
    }
}

// ---- prep: attn_input[b][d][tt] = sum_s Ve[tt][s] * x[b][s][d] ------------
__global__ void att_kernel(const float* __restrict__ x,
                           const float* __restrict__ Ve) {
    __shared__ float xr[kS * kD];
    const int b = blockIdx.x;
    const int t = threadIdx.x;            // 576 threads
    xr[t] = x[(size_t)b * (kS * kD) + t];
    __syncthreads();
    const int d = t / kS, tt = t % kS;
    float acc = 0.f;
    #pragma unroll 8
    for (int s = 0; s < kS; s++)
        acc += Ve[tt * kS + s] * xr[s * kD + d];
    g_Att[((size_t)b * kD + d) * kS + tt] = acc;
}

// ---- main fused kernel ----------------------------------------------------
__global__ __launch_bounds__(NT_, 2)
void davinci_kernel(const float* __restrict__ x,
                    const float* __restrict__ bih_e, const float* __restrict__ bhh_e,
                    const float* __restrict__ ve,
                    const float* __restrict__ vd,
                    const float* __restrict__ bih_d, const float* __restrict__ bhh_d,
                    const float* __restrict__ Wout, const float* __restrict__ bout,
                    const float* __restrict__ smean, const float* __restrict__ sstd,
                    const float* __restrict__ pmean,
                    float* __restrict__ out) {
    extern __shared__ float sm[];
    const int t   = threadIdx.x;
    const int b0  = blockIdx.x * MB_;
    const int bp0 = blockIdx.x * (MB_ / 2);       // pair base (8 pairs/block)

    float* sHpf = sm + OFF_HP;     // [128][9] f2 -> float idx (k*9+p)*2
    float* sCpf = sm + OFF_CP;
    float* sApf = sm + OFF_AP;
    float* sLgf = sm + OFF_LOG;    // [64][18]
    float* sEDp = sm + OFF_EDP;    // [9][18]
    float* sPhy = sm + OFF_PHY;    // [9][18]
    float* sPos = sm + OFF_POS;
    float* sVel = sm + OFF_VEL;
    float* sAcc = sm + OFF_ACC;
    float* sVe  = sm + OFF_VE;
    float* sVd  = sm + OFF_VD;
    float* sSc  = sm + OFF_SC;
    float* sBias= sm + OFF_BIAS;
    float* sWo  = sm + OFF_WO;
    float* sBo  = sm + OFF_BO;
    float* uni  = sm + OFF_UNION;
    float* sAtt = uni + U_ATT;                              // [16][9][65] f32
    __nv_bfloat16* sWeTb = (__nv_bfloat16*)(uni + U_WET);   // [256][65] bf16
    __nv_bfloat16* sWdTb = (__nv_bfloat16*)(uni + U_WDT);   // [256][129] bf16

    // ======================= prologue ======================================
    if (t < 64)  sVe[t] = ve[t];
    if (t < 128) sVd[t] = vd[t];
    if (t < 9)   sSc[t] = (t < 3) ? smean[t] : (t < 6 ? sstd[t - 3] : pmean[t - 6]);
    if (t < 256) { sBias[t] = bih_e[t] + bhh_e[t]; sBias[256 + t] = bih_e[256 + t] + bhh_e[256 + t]; }

    for (int i = t; i < MB_ * kD * kS; i += NT_)           // 9216, contiguous
        sAtt[(i >> 6) * 65 + (i & 63)] = g_Att[(size_t)b0 * (kD * kS) + i];
    for (int i = t; i < 256 * 64; i += NT_) {
        int k = i >> 6, s = i & 63;
        sWeTb[k * 65 + s] = g_WeTb[i];
    }
    if (t < MB_) {
        const float* xr = x + (size_t)(b0 + t) * (kS * kD);
        #pragma unroll
        for (int m = 0; m < 3; m++) {
            float p  = xr[63 * 9 + m] + sSc[6 + m];
            float v  = xr[63 * 9 + 3 + m] * sSc[3 + m] + sSc[m];
            float pv = xr[62 * 9 + 3 + m] * sSc[3 + m] + sSc[m];
            sPos[t * 4 + m] = p;
            sVel[t * 4 + m] = v;
            sAcc[t * 4 + m] = (v - pv) * (1.0f / kDT);
        }
    }
    for (int i = t; i < 2304; i += NT_) { sHpf[i] = 0.f; sCpf[i] = 0.f; }
    __syncthreads();

    // ======================= encoder loop ==================================
    for (int ts = 0; ts < kS; ts++) {
        // --- stage1: a[r][s] = W_e[s] . [h;c]  (4 rows = 2 pairs / thread)
        {
            const int s  = t & 63;
            const int pg = (t >> 6) * 2;       // 0,2,4,6
            ull a0 = 0ull, a1 = 0ull;
            #pragma unroll 8
            for (int k = 0; k < 128; k++) {
                float w = __bfloat162float(sWeTb[k * 65 + s]);
                ull w2 = pk2(w, w);
                a0 = ffma2(w2, ldp(sHpf + (k * 9 + pg) * 2), a0);
                a1 = ffma2(w2, ldp(sHpf + (k * 9 + pg + 1) * 2), a1);
            }
            #pragma unroll 8
            for (int k = 0; k < 128; k++) {
                float w = __bfloat162float(sWeTb[(128 + k) * 65 + s]);
                ull w2 = pk2(w, w);
                a0 = ffma2(w2, ldp(sCpf + (k * 9 + pg) * 2), a0);
                a1 = ffma2(w2, ldp(sCpf + (k * 9 + pg + 1) * 2), a1);
            }
            stp(sApf + (s * 9 + pg) * 2, a0);
            stp(sApf + (s * 9 + pg + 1) * 2, a1);
        }
        __syncthreads();
        // --- stage2+3 fused: e, softmax over d (shfl, 16-lane groups),
        //     x_tilde -> sEDp[d][r]
        {
            const int r = t >> 4;        // 0..15
            const int l = t & 15;        // lane in group; d = l for l<9
            float e = -1e30f;
            if (l < 9) {
                float acc = 0.f;
                #pragma unroll 4
                for (int s2 = 0; s2 < 64; s2++) {
                    float z = sApf[s2 * 18 + r] + sAtt[(r * 9 + l) * 65 + s2];
                    acc += sVe[s2] * tanhfast(z);
                }
                e = acc;
            }
            float mx = e;
            #pragma unroll
            for (int o = 8; o; o >>= 1)
                mx = fmaxf(mx, __shfl_xor_sync(0xffffffffu, mx, o, 16));
            float ex = (l < 9) ? __expf(e - mx) : 0.f;
            float sum = ex;
            #pragma unroll
            for (int o = 8; o; o >>= 1)
                sum += __shfl_xor_sync(0xffffffffu, sum, o, 16);
            if (l < 9) {
                float xv = x[(size_t)(b0 + r) * (kS * kD) + ts * kD + l];
                sEDp[l * 18 + r] = __fdividef(ex, sum) * xv;
            }
        }
        __syncthreads();
        // --- stage4: gates + LSTM update; stage5: V_d . h
        {
            const int j  = t & 127;
            const int p0 = (t >> 7) * 4;          // 0 or 4 : 4 pairs = 8 rows
            ull acc[16];                          // [gate][pair]
            {
                ull bi = pk2(sBias[j], sBias[j]);
                ull bf = pk2(sBias[128 + j], sBias[128 + j]);
                ull bg = pk2(sBias[256 + j], sBias[256 + j]);
                ull bo = pk2(sBias[384 + j], sBias[384 + j]);
                #pragma unroll
                for (int p = 0; p < 4; p++) {
                    acc[p] = bi; acc[4 + p] = bf; acc[8 + p] = bg; acc[12 + p] = bo;
                }
            }
            #pragma unroll
            for (int d = 0; d < 9; d++) {
                float4 w4 = g_Wencx4[d * 128 + j];
                ull wi = pk2(w4.x, w4.x), wf = pk2(w4.y, w4.y);
                ull wg = pk2(w4.z, w4.z), wo = pk2(w4.w, w4.w);
                #pragma unroll
                for (int p = 0; p < 4; p++) {
                    ull xv = ldp(sEDp + d * 18 + 2 * (p0 + p));
                    acc[p]      = ffma2(wi, xv, acc[p]);
                    acc[4 + p]  = ffma2(wf, xv, acc[4 + p]);
                    acc[8 + p]  = ffma2(wg, xv, acc[8 + p]);
                    acc[12 + p] = ffma2(wo, xv, acc[12 + p]);
                }
            }
            #pragma unroll 4
            for (int k = 0; k < 128; k++) {
                float4 w4 = g_Wenc4[k * 128 + j];
                ull wi = pk2(w4.x, w4.x), wf = pk2(w4.y, w4.y);
                ull wg = pk2(w4.z, w4.z), wo = pk2(w4.w, w4.w);
                #pragma unroll
                for (int p = 0; p < 4; p++) {
                    ull hv = ldp(sHpf + (k * 9 + p0 + p) * 2);
                    acc[p]      = ffma2(wi, hv, acc[p]);
                    acc[4 + p]  = ffma2(wf, hv, acc[4 + p]);
                    acc[8 + p]  = ffma2(wg, hv, acc[8 + p]);
                    acc[12 + p] = ffma2(wo, hv, acc[12 + p]);
                }
            }
            __syncthreads();
            #pragma unroll
            for (int p = 0; p < 4; p++) {
                float ai0, ai1, af0, af1, ag0, ag1, ao0, ao1, c0, c1;
                upk2(acc[p], ai0, ai1);  upk2(acc[4 + p], af0, af1);
                upk2(acc[8 + p], ag0, ag1); upk2(acc[12 + p], ao0, ao1);
                upk2(ldp(sCpf + (j * 9 + p0 + p) * 2), c0, c1);
                float cn0 = sigm(af0) * c0 + sigm(ai0) * tanhfast(ag0);
                float cn1 = sigm(af1) * c1 + sigm(ai1) * tanhfast(ag1);
                float hn0 = sigm(ao0) * tanhfast(cn0);
                float hn1 = sigm(ao1) * tanhfast(cn1);
                stp(sCpf + (j * 9 + p0 + p) * 2, pk2(cn0, cn1));
                stp(sHpf + (j * 9 + p0 + p) * 2, pk2(hn0, hn1));
                g_EncHbf[((size_t)(bp0 + p0 + p) * kS + ts) * kH + j] =
                    __float22bfloat162_rn(make_float2(hn0, hn1));
            }
            __syncthreads();
            // stage5: A[r][ho] = V_d[ho] . h  -> g_AEtbf transposed, pair bf16
            ull a5[4] = {0ull, 0ull, 0ull, 0ull};
            #pragma unroll 2
            for (int k4 = 0; k4 < 32; k4++) {
                float4 w4 = g_Vd4[k4 * 128 + j];
                #pragma unroll
                for (int kk = 0; kk < 4; kk++) {
                    float wv = (kk == 0) ? w4.x : (kk == 1) ? w4.y : (kk == 2) ? w4.z : w4.w;
                    ull w2 = pk2(wv, wv);
                    int k = 4 * k4 + kk;
                    #pragma unroll
                    for (int p = 0; p < 4; p++)
                        a5[p] = ffma2(w2, ldp(sHpf + (k * 9 + p0 + p) * 2), a5[p]);
                }
            }
            #pragma unroll
            for (int p = 0; p < 4; p++) {
                float lo, hi; upk2(a5[p], lo, hi);
                g_AEtbf[((size_t)(bp0 + p0 + p) * kH + j) * kS + ts] =
                    __float22bfloat162_rn(make_float2(lo, hi));
            }
        }
        // NOTE: no end-of-step barrier needed — stage5 and the next stage1
        // only READ sHpf/sCpf; stage1's write target (sApf) is untouched by
        // stage5, and the next write to sHpf is 3 barriers away.
    }
    __syncthreads();

    // ======================= decoder weight reload =========================
    for (int i = t; i < 256 * 128; i += NT_) {          // Wd^T bf16 into union
        int k = i >> 7, ho = i & 127;
        sWdTb[k * 129 + ho] = g_WdTb[i];
    }
    if (t < 256) { sBias[t] = bih_d[t] + bhh_d[t]; sBias[256 + t] = bih_d[256 + t] + bhh_d[256 + t]; }
    for (int i = t; i < 768; i += NT_) sWo[i] = Wout[i];
    if (t < 3) sBo[t] = bout[t];
    __syncthreads();

    // ======================= decoder loop ==================================
    for (int st = 0; st < kHZ; st++) {
        // --- s1: a[r][ho] = W_d[ho] . [d;c]   (8 rows = 4 pairs)
        {
            const int ho = t & 127;
            const int p0 = (t >> 7) * 4;
            ull a[4] = {0ull, 0ull, 0ull, 0ull};
            #pragma unroll 8
            for (int k = 0; k < 128; k++) {
                float w = __bfloat162float(sWdTb[k * 129 + ho]);
                ull w2 = pk2(w, w);
                #pragma unroll
                for (int p = 0; p < 4; p++)
                    a[p] = ffma2(w2, ldp(sHpf + (k * 9 + p0 + p) * 2), a[p]);
            }
            #pragma unroll 8
            for (int k = 0; k < 128; k++) {
                float w = __bfloat162float(sWdTb[(128 + k) * 129 + ho]);
                ull w2 = pk2(w, w);
                #pragma unroll
                for (int p = 0; p < 4; p++)
                    a[p] = ffma2(w2, ldp(sCpf + (k * 9 + p0 + p) * 2), a[p]);
            }
            #pragma unroll
            for (int p = 0; p < 4; p++) stp(sApf + (ho * 9 + p0 + p) * 2, a[p]);
        }
        __syncthreads();
        // --- s2: logits[r][s] = sum_ho v_d[ho]*tanh(a[r][ho] + AEt[ho][s])
        {
            const int s  = t & 63;
            const int g  = t >> 6;                 // 0..3
            const int r0 = g * 4;                  // rows r0..r0+3 = pairs 2g,2g+1
            float l0 = 0.f, l1 = 0.f, l2 = 0.f, l3 = 0.f;
            const __nv_bfloat162* aet0 =
                g_AEtbf + ((size_t)(bp0 + 2 * g) * kH) * kS + s;
            const __nv_bfloat162* aet1 = aet0 + (size_t)kH * kS;
            #pragma unroll 8
            for (int ho = 0; ho < 128; ho++) {
                float2 v0 = __bfloat1622float2(aet0[ho * kS]);
                float2 v1 = __bfloat1622float2(aet1[ho * kS]);
                float w  = sVd[ho];
                float a0 = sApf[ho * 18 + r0];
                float a1 = sApf[ho * 18 + r0 + 1];
                float a2 = sApf[ho * 18 + r0 + 2];
                float a3 = sApf[ho * 18 + r0 + 3];
                l0 += w * tanhfast(a0 + v0.x);
                l1 += w * tanhfast(a1 + v0.y);
                l2 += w * tanhfast(a2 + v1.x);
                l3 += w * tanhfast(a3 + v1.y);
            }
            sLgf[s * 18 + r0]     = l0;
            sLgf[s * 18 + r0 + 1] = l1;
            sLgf[s * 18 + r0 + 2] = l2;
            sLgf[s * 18 + r0 + 3] = l3;
        }
        __syncthreads();
        // --- s3: softmax beta over s (shfl, 16-lane groups, 4 s per lane);
        //     phys vector
        {
            const int r = t >> 4;
            const int l = t & 15;
            float v0 = sLgf[l * 18 + r];
            float v1 = sLgf[(l + 16) * 18 + r];
            float v2 = sLgf[(l + 32) * 18 + r];
            float v3 = sLgf[(l + 48) * 18 + r];
            float mx = fmaxf(fmaxf(v0, v1), fmaxf(v2, v3));
            #pragma unroll
            for (int o = 8; o; o >>= 1)
                mx = fmaxf(mx, __shfl_xor_sync(0xffffffffu, mx, o, 16));
            v0 = __expf(v0 - mx); v1 = __expf(v1 - mx);
            v2 = __expf(v2 - mx); v3 = __expf(v3 - mx);
            float sum = (v0 + v1) + (v2 + v3);
            #pragma unroll
            for (int o = 8; o; o >>= 1)
                sum += __shfl_xor_sync(0xffffffffu, sum, o, 16);
            float inv = __fdividef(1.f, sum);
            sLgf[l * 18 + r]        = v0 * inv;
            sLgf[(l + 16) * 18 + r] = v1 * inv;
            sLgf[(l + 32) * 18 + r] = v2 * inv;
            sLgf[(l + 48) * 18 + r] = v3 * inv;
            if (l < 9) {
                const int grp = l / 3, m = l % 3;
                float val;
                if (grp == 0)      val = sPos[r * 4 + m] - sSc[6 + m];
                else if (grp == 1) val = __fdividef(sVel[r * 4 + m] - sSc[m], sSc[3 + m]);
                else               val = __fdividef(sAcc[r * 4 + m], sSc[3 + m]);
                sPhy[l * 18 + r] = val;
            }
        }
        __syncthreads();
        // --- s4: context[r][ho] = sum_s beta[r][s]*EncH  (bf16 pairs)
        {
            const int ho = t & 127;
            const int p0 = (t >> 7) * 4;
            ull a[4] = {0ull, 0ull, 0ull, 0ull};
            const __nv_bfloat162* eh =
                g_EncHbf + ((size_t)(bp0 + p0) * kS) * kH + ho;
            #pragma unroll 8
            for (int s2 = 0; s2 < 64; s2++) {
                #pragma unroll
                for (int p = 0; p < 4; p++) {
                    float2 h2 = __bfloat1622float2(eh[(p * kS + s2) * kH]);
                    ull bv = ldp(sLgf + s2 * 18 + 2 * (p0 + p));
                    a[p] = ffma2(bv, pk2(h2.x, h2.y), a[p]);
                }
            }
            #pragma unroll
            for (int p = 0; p < 4; p++) stp(sApf + (ho * 9 + p0 + p) * 2, a[p]);
        }
        __syncthreads();
        // --- s5: decoder gates + LSTM update
        {
            const int j  = t & 127;
            const int p0 = (t >> 7) * 4;
            ull acc[16];
            {
                ull bi = pk2(sBias[j], sBias[j]);
                ull bf = pk2(sBias[128 + j], sBias[128 + j]);
                ull bg = pk2(sBias[256 + j], sBias[256 + j]);
                ull bo = pk2(sBias[384 + j], sBias[384 + j]);
                #pragma unroll
                for (int p = 0; p < 4; p++) {
                    acc[p] = bi; acc[4 + p] = bf; acc[8 + p] = bg; acc[12 + p] = bo;
                }
            }
            #pragma unroll
            for (int d = 0; d < 9; d++) {
                float4 w4 = g_Wdec4[d * 128 + j];
                ull wi = pk2(w4.x, w4.x), wf = pk2(w4.y, w4.y);
                ull wg = pk2(w4.z, w4.z), wo = pk2(w4.w, w4.w);
                #pragma unroll
                for (int p = 0; p < 4; p++) {
                    ull xv = ldp(sPhy + d * 18 + 2 * (p0 + p));
                    acc[p]      = ffma2(wi, xv, acc[p]);
                    acc[4 + p]  = ffma2(wf, xv, acc[4 + p]);
                    acc[8 + p]  = ffma2(wg, xv, acc[8 + p]);
                    acc[12 + p] = ffma2(wo, xv, acc[12 + p]);
                }
            }
            #pragma unroll 4
            for (int k = 0; k < 128; k++) {         // context part
                float4 w4 = g_Wdec4[(9 + k) * 128 + j];
                ull wi = pk2(w4.x, w4.x), wf = pk2(w4.y, w4.y);
                ull wg = pk2(w4.z, w4.z), wo = pk2(w4.w, w4.w);
                #pragma unroll
                for (int p = 0; p < 4; p++) {
                    ull xv = ldp(sApf + (k * 9 + p0 + p) * 2);
                    acc[p]      = ffma2(wi, xv, acc[p]);
                    acc[4 + p]  = ffma2(wf, xv, acc[4 + p]);
                    acc[8 + p]  = ffma2(wg, xv, acc[8 + p]);
                    acc[12 + p] = ffma2(wo, xv, acc[12 + p]);
                }
            }
            #pragma unroll 4
            for (int k = 0; k < 128; k++) {         // h part
                float4 w4 = g_Wdec4[(137 + k) * 128 + j];
                ull wi = pk2(w4.x, w4.x), wf = pk2(w4.y, w4.y);
                ull wg = pk2(w4.z, w4.z), wo = pk2(w4.w, w4.w);
                #pragma unroll
                for (int p = 0; p < 4; p++) {
                    ull hv = ldp(sHpf + (k * 9 + p0 + p) * 2);
                    acc[p]      = ffma2(wi, hv, acc[p]);
                    acc[4 + p]  = ffma2(wf, hv, acc[4 + p]);
                    acc[8 + p]  = ffma2(wg, hv, acc[8 + p]);
                    acc[12 + p] = ffma2(wo, hv, acc[12 + p]);
                }
            }
            __syncthreads();
            #pragma unroll
            for (int p = 0; p < 4; p++) {
                float ai0, ai1, af0, af1, ag0, ag1, ao0, ao1, c0, c1;
                upk2(acc[p], ai0, ai1);  upk2(acc[4 + p], af0, af1);
                upk2(acc[8 + p], ag0, ag1); upk2(acc[12 + p], ao0, ao1);
                upk2(ldp(sCpf + (j * 9 + p0 + p) * 2), c0, c1);
                float cn0 = sigm(af0) * c0 + sigm(ai0) * tanhfast(ag0);
                float cn1 = sigm(af1) * c1 + sigm(ai1) * tanhfast(ag1);
                float dn0 = sigm(ao0) * tanhfast(cn0);
                float dn1 = sigm(ao1) * tanhfast(cn1);
                stp(sCpf + (j * 9 + p0 + p) * 2, pk2(cn0, cn1));
                stp(sHpf + (j * 9 + p0 + p) * 2, pk2(dn0, dn1));
            }
        }
        __syncthreads();
        // --- s6: pred_acc + Verlet + output (192 threads, quad-split dots)
        if (t < 192) {
            const int q = t & 3;           // quad lane
            const int o = t >> 2;          // 0..47
            const int m = o >> 4;          // 0..2
            const int r = o & 15;
            const float* src = (q < 2) ? sHpf : sApf;
            const int kbase = (q & 1) * 64;
            const float* w = sWo + m * 256 + (q >> 1) * 128 + kbase;
            float acc = 0.f;
            #pragma unroll 4
            for (int kk = 0; kk < 64; kk++)
                acc += w[kk] * src[(kbase + kk) * 18 + r];
            acc += __shfl_xor_sync(0xffffffffu, acc, 1, 4);
            acc += __shfl_xor_sync(0xffffffffu, acc, 2, 4);
            if (q == 0) {
                acc += sBo[m];
                float pa   = acc * sSc[3 + m];
                float pos  = sPos[r * 4 + m];
                float vel  = sVel[r * 4 + m];
                float ac   = sAcc[r * 4 + m];
                float posn = pos + vel * kDT + 0.5f * ac * kDT * kDT;
                float veln = vel + 0.5f * (ac + pa) * kDT;
                float* orow = out + ((size_t)(b0 + r) * kHZ + st) * 9;
                orow[m]     = posn;
                orow[3 + m] = veln;
                orow[6 + m] = pa;
                sPos[r * 4 + m] = posn;
                sVel[r * 4 + m] = veln;
                sAcc[r * 4 + m] = pa;
            }
        }
        __syncthreads();
    }
}

// ---------------------------------------------------------------------------
extern "C" void kernel_launch(void* const* d_in, const int* in_sizes, int n_in,
                              void* d_out, int out_size) {
    const float* x      = (const float*)d_in[0];
    const float* Wih_e  = (const float*)d_in[1];
    const float* Whh_e  = (const float*)d_in[2];
    const float* bih_e  = (const float*)d_in[3];
    const float* bhh_e  = (const float*)d_in[4];
    const float* We     = (const float*)d_in[5];
    const float* Ve     = (const float*)d_in[6];
    const float* ve     = (const float*)d_in[7];
    const float* Wd     = (const float*)d_in[8];
    const float* Vd     = (const float*)d_in[9];
    const float* vd     = (const float*)d_in[10];
    const float* Wih_d  = (const float*)d_in[11];
    const float* Whh_d  = (const float*)d_in[12];
    const float* bih_d  = (const float*)d_in[13];
    const float* bhh_d  = (const float*)d_in[14];
    const float* Wout   = (const float*)d_in[15];
    const float* bout   = (const float*)d_in[16];
    const float* smean  = (const float*)d_in[17];
    const float* sstd   = (const float*)d_in[18];
    const float* pmean  = (const float*)d_in[19];
    float* out = (float*)d_out;

    cudaFuncSetAttribute(davinci_kernel,
                         cudaFuncAttributeMaxDynamicSharedMemorySize, SMEM_BYTES);

    prep_kernel<<<(265 * 128 + 255) / 256, 256>>>(Whh_e, Wih_e, Whh_d, Wih_d, Vd, We, Wd);
    att_kernel<<<kB, kS * kD>>>(x, Ve);
    davinci_kernel<<<kB / MB_, NT_, SMEM_BYTES>>>(
        x, bih_e, bhh_e, ve, vd,
        bih_d, bhh_d, Wout, bout, smean, sstd, pmean, out);
}